// round 1
// baseline (speedup 1.0000x reference)
#include <cuda_runtime.h>

#define B_    32
#define N_    8
#define CIN   3
#define HWD   224
#define PATCH 32
#define S_    49
#define C_    384
#define HM_   512
#define CO_   256
#define NP    (B_*N_*S_)          /* 12544 */
#define KCONV (CIN*PATCH*PATCH)   /* 3072  */
#define NE    (B_*N_*N_)          /* 2048  */

// ---- scratch (static device globals; no allocation) ----
__device__ float g_feats[NP * C_];   // 12544 x 384
__device__ float g_a[NP * HM_];      // 12544 x 512
__device__ float g_g[NP * HM_];      // 12544 x 512
__device__ float g_mask[NE];         // 2048

// ============================================================
// Kernel 1: patch embedding as GEMM
//   feats[p, c] = sum_k img_patch[p, k] * W_patch[c, k] + b_patch[c]
//   M=12544, N=384, K=3072. Tiles: 64x64x16, 4x4 reg tile, 256 thr.
// ============================================================
__global__ void patch_embed_kernel(const float* __restrict__ img,
                                   const float* __restrict__ Wp,
                                   const float* __restrict__ bp)
{
    __shared__ float As[16][68];
    __shared__ float Bs[16][68];

    const int tid = threadIdx.x;
    const int bm  = blockIdx.x * 64;
    const int bn  = blockIdx.y * 64;
    const int ty  = tid >> 4;          // 0..15
    const int tx  = tid & 15;          // 0..15
    const int lk  = tid & 15;          // loader k index
    const int lm  = tid >> 4;          // loader row base

    // precompute image base offsets for the 4 A rows this thread loads
    long rowbase[4];
#pragma unroll
    for (int i = 0; i < 4; i++) {
        int p  = bm + lm + i * 16;
        int n  = p / 49;
        int s  = p - n * 49;
        int py = s / 7;
        int px = s - py * 7;
        rowbase[i] = ((long)n * CIN * HWD + (long)py * PATCH) * HWD + (long)px * PATCH;
    }

    float acc[4][4];
#pragma unroll
    for (int i = 0; i < 4; i++)
#pragma unroll
        for (int j = 0; j < 4; j++) acc[i][j] = 0.f;

    for (int kc = 0; kc < KCONV; kc += 16) {
        int k   = kc + lk;
        int ci  = k >> 10;
        int rem = k & 1023;
        int y   = rem >> 5;
        int x   = rem & 31;
        long off = (long)ci * HWD * HWD + (long)y * HWD + x;
#pragma unroll
        for (int i = 0; i < 4; i++)
            As[lk][lm + i * 16] = img[rowbase[i] + off];
#pragma unroll
        for (int i = 0; i < 4; i++)
            Bs[lk][lm + i * 16] = Wp[(long)(bn + lm + i * 16) * KCONV + k];
        __syncthreads();
#pragma unroll
        for (int kk = 0; kk < 16; kk++) {
            float4 av = *(const float4*)&As[kk][ty * 4];
            float4 bv = *(const float4*)&Bs[kk][tx * 4];
            float a0[4] = {av.x, av.y, av.z, av.w};
            float b0[4] = {bv.x, bv.y, bv.z, bv.w};
#pragma unroll
            for (int i = 0; i < 4; i++)
#pragma unroll
                for (int j = 0; j < 4; j++)
                    acc[i][j] = fmaf(a0[i], b0[j], acc[i][j]);
        }
        __syncthreads();
    }

#pragma unroll
    for (int i = 0; i < 4; i++) {
        int p = bm + ty * 4 + i;
#pragma unroll
        for (int j = 0; j < 4; j++) {
            int c = bn + tx * 4 + j;
            g_feats[(long)p * C_ + c] = acc[i][j] + bp[c];
        }
    }
}

// ============================================================
// Kernel 2: a = feats @ W1a, g = feats @ W1b  (no bias; b1 added later)
//   M=12544, K=384, N=512 each. blockIdx.y: 0..7 -> a tiles, 8..15 -> g tiles
// ============================================================
__global__ void ag_gemm_kernel(const float* __restrict__ W1a,
                               const float* __restrict__ W1b)
{
    __shared__ float As[16][68];
    __shared__ float Bs[16][64];

    const int tid = threadIdx.x;
    const int bm  = blockIdx.x * 64;
    const int nt  = blockIdx.y;
    const float* W1;
    float* out;
    int bn;
    if (nt < 8) { W1 = W1a; out = g_a; bn = nt * 64; }
    else        { W1 = W1b; out = g_g; bn = (nt - 8) * 64; }

    const int ty = tid >> 4, tx = tid & 15;
    const int lk = tid & 15, lm = tid >> 4;   // A loader
    const int kb = tid >> 6, cb = tid & 63;   // B loader

    float acc[4][4];
#pragma unroll
    for (int i = 0; i < 4; i++)
#pragma unroll
        for (int j = 0; j < 4; j++) acc[i][j] = 0.f;

    for (int kc = 0; kc < C_; kc += 16) {
#pragma unroll
        for (int i = 0; i < 4; i++)
            As[lk][lm + i * 16] = g_feats[(long)(bm + lm + i * 16) * C_ + kc + lk];
#pragma unroll
        for (int i = 0; i < 4; i++)
            Bs[kb + i * 4][cb] = W1[(long)(kc + kb + i * 4) * HM_ + bn + cb];
        __syncthreads();
#pragma unroll
        for (int kk = 0; kk < 16; kk++) {
            float4 av = *(const float4*)&As[kk][ty * 4];
            float4 bv = *(const float4*)&Bs[kk][tx * 4];
            float a0[4] = {av.x, av.y, av.z, av.w};
            float b0[4] = {bv.x, bv.y, bv.z, bv.w};
#pragma unroll
            for (int i = 0; i < 4; i++)
#pragma unroll
                for (int j = 0; j < 4; j++)
                    acc[i][j] = fmaf(a0[i], b0[j], acc[i][j]);
        }
        __syncthreads();
    }

#pragma unroll
    for (int i = 0; i < 4; i++) {
        int p = bm + ty * 4 + i;
#pragma unroll
        for (int j = 0; j < 4; j++)
            out[(long)p * HM_ + bn + tx * 4 + j] = acc[i][j];
    }
}

// ============================================================
// Kernel 3: communication mask (also writes mask section of output)
// ============================================================
__global__ void mask_kernel(const float* __restrict__ pos, float* __restrict__ out)
{
    int e = blockIdx.x * blockDim.x + threadIdx.x;
    if (e >= NE) return;
    int b = e >> 6;
    int i = (e >> 3) & 7;
    int j = e & 7;
    float xi = pos[(b * N_ + i) * 3 + 0], yi = pos[(b * N_ + i) * 3 + 1];
    float xj = pos[(b * N_ + j) * 3 + 0], yj = pos[(b * N_ + j) * 3 + 1];
    float dx = xi - xj, dy = yi - yj;
    // exact mul/add order (no fused FMA) to match reference rounding at boundary
    float d2 = __fadd_rn(__fmul_rn(dx, dx), __fmul_rn(dy, dy));
    float m = (d2 < 0.25f && i != j) ? 1.0f : 0.0f;
    g_mask[e] = m;
    out[NE * 7 + e] = m;   // mask output section
}

// ============================================================
// Kernel 4: fused edge MLP + heads.
//   One block per edge. Early-exit for masked edges (output = 0).
//   m[o] = b2[o] + (1/49) * sum_{s,h} relu(a[i,s,h]+g[j,s,h]+b1[h]) * W2[h,o]
//   heads: 7 dot products of m with Wp/Wpv/Wr/Wrv columns + biases.
// ============================================================
__global__ void __launch_bounds__(256, 4)
edge_kernel(const float* __restrict__ b1, const float* __restrict__ W2,
            const float* __restrict__ b2,
            const float* __restrict__ Wph, const float* __restrict__ bph,
            const float* __restrict__ Wpv, const float* __restrict__ bpv,
            const float* __restrict__ Wr,  const float* __restrict__ br,
            const float* __restrict__ Wrv, const float* __restrict__ brv,
            float* __restrict__ out)
{
    __shared__ float h_tile[49 * 128];
    __shared__ float partial[4 * 256];
    __shared__ float red[7][8];

    const int e   = blockIdx.x;
    const int tid = threadIdx.x;

    float mf = g_mask[e];
    if (mf == 0.0f) {
        if (tid < 7) out[e * 7 + tid] = 0.0f;
        return;
    }

    const int b = e >> 6, i = (e >> 3) & 7, j = e & 7;
    const float* ap = g_a + (long)((b * 8 + i) * 49) * HM_;
    const float* gp = g_g + (long)((b * 8 + j) * 49) * HM_;

    const int hg = tid >> 6;      // 0..3: splits HM chunk
    const int lane = tid & 63;    // owns outputs 4*lane .. 4*lane+3

    float4 acc = make_float4(0.f, 0.f, 0.f, 0.f);

    for (int hc = 0; hc < HM_; hc += 128) {
        __syncthreads();
        // build h tile: relu(a + g + b1), 49 x 128
        for (int idx = tid; idx < 49 * 128; idx += 256) {
            int s  = idx >> 7;
            int hh = idx & 127;
            int h  = hc + hh;
            float v = ap[s * HM_ + h] + gp[s * HM_ + h] + b1[h];
            h_tile[idx] = v > 0.f ? v : 0.f;
        }
        __syncthreads();
        // accumulate: this warp-group handles hh in [hg*32, hg*32+32)
        const int hh0 = hg * 32;
#pragma unroll 2
        for (int hh = hh0; hh < hh0 + 32; hh++) {
            float4 w = *(const float4*)&W2[(long)(hc + hh) * CO_ + lane * 4];
#pragma unroll
            for (int s = 0; s < 49; s++) {
                float hv = h_tile[s * 128 + hh];
                acc.x = fmaf(hv, w.x, acc.x);
                acc.y = fmaf(hv, w.y, acc.y);
                acc.z = fmaf(hv, w.z, acc.z);
                acc.w = fmaf(hv, w.w, acc.w);
            }
        }
    }

    // reduce partials across the 4 warp-groups
    *(float4*)&partial[hg * 256 + lane * 4] = acc;
    __syncthreads();

    float mo = (partial[tid] + partial[256 + tid] + partial[512 + tid] + partial[768 + tid])
               * (1.0f / 49.0f) + b2[tid];

    // 7 head dot-products, block-reduced
    float pr[7];
    pr[0] = mo * Wph[tid * 2];     pr[1] = mo * Wph[tid * 2 + 1];
    pr[2] = mo * Wpv[tid * 2];     pr[3] = mo * Wpv[tid * 2 + 1];
    pr[4] = mo * Wr[tid * 2];      pr[5] = mo * Wr[tid * 2 + 1];
    pr[6] = mo * Wrv[tid];
#pragma unroll
    for (int k = 0; k < 7; k++) {
        float v = pr[k];
#pragma unroll
        for (int off = 16; off; off >>= 1)
            v += __shfl_down_sync(0xffffffffu, v, off);
        if ((tid & 31) == 0) red[k][tid >> 5] = v;
    }
    __syncthreads();
    if (tid < 7) {
        float v = 0.f;
#pragma unroll
        for (int w = 0; w < 8; w++) v += red[tid][w];
        float bias;
        switch (tid) {
            case 0: bias = bph[0]; break;
            case 1: bias = bph[1]; break;
            case 2: bias = bpv[0]; break;
            case 3: bias = bpv[1]; break;
            case 4: bias = br[0];  break;
            case 5: bias = br[1];  break;
            default: bias = brv[0];
        }
        out[e * 7 + tid] = v + bias;   // mf == 1 here
    }
}

// ============================================================
// Kernel 5: zero-fill node_preds section
// ============================================================
__global__ void zero_kernel(float* __restrict__ out, int n0, int n1)
{
    int idx = n0 + blockIdx.x * blockDim.x + threadIdx.x;
    if (idx < n1) out[idx] = 0.0f;
}

// ============================================================
extern "C" void kernel_launch(void* const* d_in, const int* in_sizes, int n_in,
                              void* d_out, int out_size)
{
    const float* img    = (const float*)d_in[0];
    const float* pos    = (const float*)d_in[1];
    /* d_in[2] = rot, unused */
    const float* Wpatch = (const float*)d_in[3];
    const float* bpatch = (const float*)d_in[4];
    const float* W1a    = (const float*)d_in[5];
    const float* W1b    = (const float*)d_in[6];
    const float* b1     = (const float*)d_in[7];
    const float* W2     = (const float*)d_in[8];
    const float* b2     = (const float*)d_in[9];
    const float* Wp     = (const float*)d_in[10];
    const float* bp     = (const float*)d_in[11];
    const float* Wpv    = (const float*)d_in[12];
    const float* bpv    = (const float*)d_in[13];
    const float* Wr     = (const float*)d_in[14];
    const float* br     = (const float*)d_in[15];
    const float* Wrv    = (const float*)d_in[16];
    const float* brv    = (const float*)d_in[17];
    float* out = (float*)d_out;

    // 1) patch embedding (feats)
    patch_embed_kernel<<<dim3(NP / 64, C_ / 64), 256>>>(img, Wpatch, bpatch);
    // 2) a / g projections
    ag_gemm_kernel<<<dim3(NP / 64, 16), 256>>>(W1a, W1b);
    // 3) mask
    mask_kernel<<<(NE + 255) / 256, 256>>>(pos, out);
    // 4) fused edge MLP + heads
    edge_kernel<<<NE, 256>>>(b1, W2, b2, Wp, bp, Wpv, bpv, Wr, br, Wrv, brv, out);
    // 5) node_preds zeros
    int n0 = NE * 7 + NE;             // 16384
    int n1 = out_size;
    int cnt = n1 - n0;
    if (cnt > 0)
        zero_kernel<<<(cnt + 255) / 256, 256>>>(out, n0, n1);
}